// round 10
// baseline (speedup 1.0000x reference)
#include <cuda_runtime.h>
#include <cuda_bf16.h>
#include <math_constants.h>

// Problem constants
#define NQ   2048
#define NK   100000
#define NKP  100032          // padded to multiple of 64
#define DIM  128
#define KSEL 50
#define DELTA 1e-3f

// Scratch (device globals: allocation-free rule)
__device__ float g_D[(size_t)NQ * NKP];   // fp32 distance matrix, ~819 MB
__device__ float g_qn[NQ];
__device__ float g_kn[NKP];

// ---------------------------------------------------------------------------
// K1: row norms, replicating XLA:CPU strict reduce semantics:
//   sum(x*x) over the minor dim = SERIAL SCALAR chain in index order,
//   multiply then add, NO fma contraction, NO vector accumulators.
//   acc = fadd(acc, fmul(x_j, x_j)),  j = 0..127
// One thread per row.
// ---------------------------------------------------------------------------
__global__ __launch_bounds__(256) void norms_kernel(
    const float* __restrict__ Q, const float* __restrict__ Kk)
{
    int i = blockIdx.x * blockDim.x + threadIdx.x;
    if (i >= NQ + NKP) return;

    const float* row;
    float* dst;
    if (i < NQ) {
        row = Q + (size_t)i * DIM;
        dst = &g_qn[i];
    } else {
        int n = i - NQ;
        if (n >= NK) { g_kn[n] = CUDART_INF_F; return; }
        row = Kk + (size_t)n * DIM;
        dst = &g_kn[n];
    }

    float acc = 0.f;
    const float4* r4 = reinterpret_cast<const float4*>(row);
    #pragma unroll 8
    for (int j = 0; j < DIM / 4; j++) {
        float4 v = __ldg(r4 + j);
        acc = __fadd_rn(acc, __fmul_rn(v.x, v.x));
        acc = __fadd_rn(acc, __fmul_rn(v.y, v.y));
        acc = __fadd_rn(acc, __fmul_rn(v.z, v.z));
        acc = __fadd_rn(acc, __fmul_rn(v.w, v.w));
    }
    *dst = acc;
}

// ---------------------------------------------------------------------------
// K2: fp32 distance matrix, 64x64 tile per CTA, full K=128 in smem.
// dot = serial FMA chain over k=0..127 (Eigen gebp order: contraction dim
//       ascending, single accumulator per output, fused multiply-add).
// d   = ((qn - 2*dot) + kn)  -- exact reference association, no re-fusion.
// ---------------------------------------------------------------------------
__global__ __launch_bounds__(256) void dist_kernel(
    const float* __restrict__ Q, const float* __restrict__ Kk)
{
    __shared__ float Qs[DIM][65];   // [k][m]
    __shared__ float Ks[DIM][65];   // [k][n]

    const int bm = blockIdx.y * 64;
    const int bn = blockIdx.x * 64;
    const int tid = threadIdx.x;

    #pragma unroll
    for (int it = 0; it < 8; it++) {
        int idx = tid + it * 256;          // 0..2047 float4 slots
        int r   = idx >> 5;                // row within tile 0..63
        int kq  = (idx & 31) << 2;         // k offset 0..124

        float4 v = reinterpret_cast<const float4*>(Q + (size_t)(bm + r) * DIM + kq)[0];
        Qs[kq + 0][r] = v.x; Qs[kq + 1][r] = v.y;
        Qs[kq + 2][r] = v.z; Qs[kq + 3][r] = v.w;

        int n = bn + r;
        float4 w = make_float4(0.f, 0.f, 0.f, 0.f);
        if (n < NK)
            w = reinterpret_cast<const float4*>(Kk + (size_t)n * DIM + kq)[0];
        Ks[kq + 0][r] = w.x; Ks[kq + 1][r] = w.y;
        Ks[kq + 2][r] = w.z; Ks[kq + 3][r] = w.w;
    }
    __syncthreads();

    const int tx = tid & 15;    // key dir
    const int ty = tid >> 4;    // query dir
    const int m0 = ty * 4, n0 = tx * 4;

    float acc[4][4];
    #pragma unroll
    for (int i = 0; i < 4; i++)
        #pragma unroll
        for (int j = 0; j < 4; j++) acc[i][j] = 0.f;

    // Serial FMA chain over k (ascending, single accumulator per output).
    #pragma unroll 8
    for (int k = 0; k < DIM; k++) {
        float a0 = Qs[k][m0 + 0], a1 = Qs[k][m0 + 1];
        float a2 = Qs[k][m0 + 2], a3 = Qs[k][m0 + 3];
        float b0 = Ks[k][n0 + 0], b1 = Ks[k][n0 + 1];
        float b2 = Ks[k][n0 + 2], b3 = Ks[k][n0 + 3];
        acc[0][0] = __fmaf_rn(a0, b0, acc[0][0]);
        acc[0][1] = __fmaf_rn(a0, b1, acc[0][1]);
        acc[0][2] = __fmaf_rn(a0, b2, acc[0][2]);
        acc[0][3] = __fmaf_rn(a0, b3, acc[0][3]);
        acc[1][0] = __fmaf_rn(a1, b0, acc[1][0]);
        acc[1][1] = __fmaf_rn(a1, b1, acc[1][1]);
        acc[1][2] = __fmaf_rn(a1, b2, acc[1][2]);
        acc[1][3] = __fmaf_rn(a1, b3, acc[1][3]);
        acc[2][0] = __fmaf_rn(a2, b0, acc[2][0]);
        acc[2][1] = __fmaf_rn(a2, b1, acc[2][1]);
        acc[2][2] = __fmaf_rn(a2, b2, acc[2][2]);
        acc[2][3] = __fmaf_rn(a2, b3, acc[2][3]);
        acc[3][0] = __fmaf_rn(a3, b0, acc[3][0]);
        acc[3][1] = __fmaf_rn(a3, b1, acc[3][1]);
        acc[3][2] = __fmaf_rn(a3, b2, acc[3][2]);
        acc[3][3] = __fmaf_rn(a3, b3, acc[3][3]);
    }

    const int gm = bm + m0;
    const int gn = bn + n0;
    #pragma unroll
    for (int i = 0; i < 4; i++) {
        float qv = g_qn[gm + i];
        float4 d;
        d.x = __fadd_rn(__fsub_rn(qv, __fmul_rn(2.f, acc[i][0])), g_kn[gn + 0]);
        d.y = __fadd_rn(__fsub_rn(qv, __fmul_rn(2.f, acc[i][1])), g_kn[gn + 1]);
        d.z = __fadd_rn(__fsub_rn(qv, __fmul_rn(2.f, acc[i][2])), g_kn[gn + 2]);
        d.w = __fadd_rn(__fsub_rn(qv, __fmul_rn(2.f, acc[i][3])), g_kn[gn + 3]);
        reinterpret_cast<float4*>(g_D + (size_t)(gm + i) * NKP + gn)[0] = d;
    }
}

// ---------------------------------------------------------------------------
// K3: per-query EXACT top-50 of the fp32 d values (tie-break by index, same as
// lax.top_k stable order), then fp64 weight epilogue (insensitive at ~1e-7).
// ---------------------------------------------------------------------------
#define CAP 2048

__device__ __forceinline__ void bitonic_sort(unsigned long long* keys, int tid)
{
    for (int k = 2; k <= CAP; k <<= 1) {
        for (int j = k >> 1; j > 0; j >>= 1) {
            #pragma unroll
            for (int t = 0; t < CAP / 256; t++) {
                int i = tid + t * 256;
                int ixj = i ^ j;
                if (ixj > i) {
                    bool up = ((i & k) == 0);
                    unsigned long long a = keys[i], b = keys[ixj];
                    if ((a > b) == up) { keys[i] = b; keys[ixj] = a; }
                }
            }
            __syncthreads();
        }
    }
}

__global__ __launch_bounds__(256) void select_kernel(
    const float* __restrict__ Q, const float* __restrict__ Kk,
    const float* __restrict__ V, float* __restrict__ out)
{
    __shared__ unsigned long long keys[CAP];
    __shared__ int   cnt;
    __shared__ float thr;
    __shared__ double d64s[KSEL];
    __shared__ __align__(16) float qs[DIM];

    const int q   = blockIdx.x;
    const int tid = threadIdx.x;

    if (tid == 0) { cnt = 0; thr = CUDART_INF_F; }
    if (tid < DIM) qs[tid] = Q[(size_t)q * DIM + tid];
    __syncthreads();

    const float4* Drow = reinterpret_cast<const float4*>(g_D + (size_t)q * NKP);
    const int n4 = NKP / 4;   // 25008

    for (int base = 0; base < n4; base += 256) {
        int i4 = base + tid;
        if (i4 < n4) {
            float4 v = Drow[i4];
            float t = thr;
            float dv[4] = {v.x, v.y, v.z, v.w};
            #pragma unroll
            for (int c = 0; c < 4; c++) {
                if (dv[c] <= t) {
                    int p = atomicAdd(&cnt, 1);
                    keys[p] = ((unsigned long long)__float_as_uint(dv[c]) << 32)
                              | (unsigned)(i4 * 4 + c);
                }
            }
        }
        __syncthreads();
        if (cnt > CAP - 1024) {            // flush: max 1024 inserts per round
            int c0 = cnt;
            for (int i = c0 + tid; i < CAP; i += 256) keys[i] = ~0ull;
            __syncthreads();
            bitonic_sort(keys, tid);
            if (tid == 0) {
                thr = __uint_as_float((unsigned)(keys[KSEL - 1] >> 32));
                cnt = KSEL;
            }
            for (int i = KSEL + tid; i < CAP; i += 256) keys[i] = ~0ull;
        }
        __syncthreads();
    }

    // final exact sort: keys[0..49] = top-50 of the fp32 d's by (d, idx)
    {
        int c0 = cnt;
        for (int i = c0 + tid; i < CAP; i += 256) keys[i] = ~0ull;
        __syncthreads();
        bitonic_sort(keys, tid);
    }

    // fp64 rescore of the 50 winners (weights insensitive to this precision).
    const int lane = tid & 31;
    const int w    = tid >> 5;
    for (int j = w; j < KSEL; j += 8) {
        unsigned idx = (unsigned)(keys[j] & 0xFFFFFFFFu);
        float4 kv = reinterpret_cast<const float4*>(Kk + (size_t)idx * DIM)[lane];
        float4 qv = reinterpret_cast<const float4*>(qs)[lane];
        double dx = (double)qv.x - (double)kv.x;
        double dy = (double)qv.y - (double)kv.y;
        double dz = (double)qv.z - (double)kv.z;
        double dw = (double)qv.w - (double)kv.w;
        double s = dx * dx + dy * dy + dz * dz + dw * dw;
        #pragma unroll
        for (int o = 16; o; o >>= 1) s += __shfl_xor_sync(0xFFFFFFFFu, s, o);
        if (lane == 0) d64s[j] = s;
    }
    __syncthreads();

    if (tid == 0) {
        double usum = 0.0;
        #pragma unroll 1
        for (int j = 0; j < KSEL; j++) usum += 1.0 / (d64s[j] + (double)DELTA);
        double o = 0.0;
        #pragma unroll 1
        for (int j = 0; j < KSEL; j++) {
            unsigned idx = (unsigned)(keys[j] & 0xFFFFFFFFu);
            o += (1.0 / (d64s[j] + (double)DELTA)) / usum * (double)V[idx];
        }
        out[q] = (float)o;
    }
}

// ---------------------------------------------------------------------------
extern "C" void kernel_launch(void* const* d_in, const int* in_sizes, int n_in,
                              void* d_out, int out_size)
{
    const float* Q  = (const float*)d_in[0];   // [2048, 128]
    const float* Kk = (const float*)d_in[1];   // [100000, 128]
    const float* V  = (const float*)d_in[2];   // [100000]
    float* out      = (float*)d_out;           // [2048, 1]

    // K1: norms, one thread per row, strict serial-scalar reduce.
    int rows = NQ + NKP;                       // 102080
    norms_kernel<<<(rows + 255) / 256, 256>>>(Q, Kk);

    // K2: distance matrix.
    dim3 g2(NKP / 64, NQ / 64);                // (1563, 32)
    dist_kernel<<<g2, 256>>>(Q, Kk);

    // K3: selection + aggregation.
    select_kernel<<<NQ, 256>>>(Q, Kk, V, out);
}

// round 11
// speedup vs baseline: 1.4001x; 1.4001x over previous
#include <cuda_runtime.h>
#include <cuda_bf16.h>
#include <math_constants.h>

// Problem constants
#define NQ   2048
#define NK   100000
#define NKP  100096          // padded to multiple of 128 (n-tile)
#define DIM  128
#define KSEL 50
#define DELTA 1e-3f

// GEMM tiling
#define TM 128
#define TN 128
#define TK 32

// Scratch (device globals: allocation-free rule)
__device__ float g_D[(size_t)NQ * NKP];   // fp32 distance matrix, ~820 MB
__device__ float g_qn[NQ];
__device__ float g_kn[NKP];

// ---- f32x2 packed helpers (each component = exact fp32 .rn op) -------------
__device__ __forceinline__ unsigned long long pack_dup(float v) {
    unsigned long long r;
    unsigned u = __float_as_uint(v);
    asm("mov.b64 %0, {%1, %2};" : "=l"(r) : "r"(u), "r"(u));
    return r;
}
__device__ __forceinline__ void fma2(unsigned long long& d,
                                     unsigned long long a,
                                     unsigned long long b) {
    asm("fma.rn.f32x2 %0, %1, %2, %3;" : "=l"(d) : "l"(a), "l"(b), "l"(d));
}
__device__ __forceinline__ void unpack2(unsigned long long v, float& lo, float& hi) {
    unsigned a, b;
    asm("mov.b64 {%0, %1}, %2;" : "=r"(a), "=r"(b) : "l"(v));
    lo = __uint_as_float(a);
    hi = __uint_as_float(b);
}

// ---------------------------------------------------------------------------
// K1: row norms, XLA:CPU strict reduce semantics: serial scalar chain in index
// order, multiply then add, NO fma. One thread per row.
// ---------------------------------------------------------------------------
__global__ __launch_bounds__(256) void norms_kernel(
    const float* __restrict__ Q, const float* __restrict__ Kk)
{
    int i = blockIdx.x * blockDim.x + threadIdx.x;
    if (i >= NQ + NKP) return;

    const float* row;
    float* dst;
    if (i < NQ) {
        row = Q + (size_t)i * DIM;
        dst = &g_qn[i];
    } else {
        int n = i - NQ;
        if (n >= NK) { g_kn[n] = CUDART_INF_F; return; }
        row = Kk + (size_t)n * DIM;
        dst = &g_kn[n];
    }

    float acc = 0.f;
    const float4* r4 = reinterpret_cast<const float4*>(row);
    #pragma unroll 8
    for (int j = 0; j < DIM / 4; j++) {
        float4 v = __ldg(r4 + j);
        acc = __fadd_rn(acc, __fmul_rn(v.x, v.x));
        acc = __fadd_rn(acc, __fmul_rn(v.y, v.y));
        acc = __fadd_rn(acc, __fmul_rn(v.z, v.z));
        acc = __fadd_rn(acc, __fmul_rn(v.w, v.w));
    }
    *dst = acc;
}

// ---------------------------------------------------------------------------
// K2: fp32 distance matrix via packed FFMA2. 128x128 CTA tile, 8x8 per thread
// with the m-dimension packed in f32x2 pairs. Each output keeps a single fp32
// accumulator updated by one exact .rn FMA per k, k ascending (Eigen gebp
// order) -- bit-identical to the scalar serial chain.
// d = ((qn - 2*dot) + kn), exact reference association.
// ---------------------------------------------------------------------------
__global__ __launch_bounds__(256, 2) void dist_kernel(
    const float* __restrict__ Q, const float* __restrict__ Kk)
{
    __shared__ float Qs[TK][TM + 4];   // [k][m]
    __shared__ float Ks[TK][TN + 4];   // [k][n]

    const int bm = blockIdx.y * TM;
    const int bn = blockIdx.x * TN;
    const int tid = threadIdx.x;
    const int tx = tid & 15;     // n dir
    const int ty = tid >> 4;     // m dir
    const int m0 = ty * 8, n0 = tx * 8;

    unsigned long long acc[4][8];   // [m-pair][n], each = (m even, m odd)
    #pragma unroll
    for (int i = 0; i < 4; i++)
        #pragma unroll
        for (int j = 0; j < 8; j++) acc[i][j] = 0ull;

    #pragma unroll 1
    for (int kc = 0; kc < DIM; kc += TK) {
        // Load 128x32 tiles of Q and K, transposed into [k][row].
        #pragma unroll
        for (int it = 0; it < 4; it++) {
            int f  = tid + it * 256;        // float4 slot 0..1023
            int r  = f >> 3;                // row within tile 0..127
            int kq = (f & 7) << 2;          // k offset 0,4,..,28

            float4 v = *reinterpret_cast<const float4*>(
                Q + (size_t)(bm + r) * DIM + kc + kq);
            Qs[kq + 0][r] = v.x; Qs[kq + 1][r] = v.y;
            Qs[kq + 2][r] = v.z; Qs[kq + 3][r] = v.w;

            int n = bn + r;
            float4 w = make_float4(0.f, 0.f, 0.f, 0.f);
            if (n < NK)
                w = *reinterpret_cast<const float4*>(
                    Kk + (size_t)n * DIM + kc + kq);
            Ks[kq + 0][r] = w.x; Ks[kq + 1][r] = w.y;
            Ks[kq + 2][r] = w.z; Ks[kq + 3][r] = w.w;
        }
        __syncthreads();

        #pragma unroll 8
        for (int k = 0; k < TK; k++) {
            // a: 4 packed m-pairs (consecutive m), directly from smem
            const ulonglong2 a01 = *reinterpret_cast<const ulonglong2*>(&Qs[k][m0]);
            const ulonglong2 a23 = *reinterpret_cast<const ulonglong2*>(&Qs[k][m0 + 4]);
            unsigned long long ap[4] = {a01.x, a01.y, a23.x, a23.y};

            const float4 bv0 = *reinterpret_cast<const float4*>(&Ks[k][n0]);
            const float4 bv1 = *reinterpret_cast<const float4*>(&Ks[k][n0 + 4]);
            unsigned long long bd[8];
            bd[0] = pack_dup(bv0.x); bd[1] = pack_dup(bv0.y);
            bd[2] = pack_dup(bv0.z); bd[3] = pack_dup(bv0.w);
            bd[4] = pack_dup(bv1.x); bd[5] = pack_dup(bv1.y);
            bd[6] = pack_dup(bv1.z); bd[7] = pack_dup(bv1.w);

            #pragma unroll
            for (int i = 0; i < 4; i++)
                #pragma unroll
                for (int j = 0; j < 8; j++)
                    fma2(acc[i][j], ap[i], bd[j]);
        }
        __syncthreads();
    }

    // Epilogue: exact reference association, no re-fusion.
    const int gn = bn + n0;
    float kn[8];
    #pragma unroll
    for (int j = 0; j < 8; j++) kn[j] = g_kn[gn + j];

    #pragma unroll
    for (int i = 0; i < 4; i++) {
        const int gm = bm + m0 + 2 * i;
        const float qn0 = g_qn[gm];
        const float qn1 = g_qn[gm + 1];
        float lo[8], hi[8];
        #pragma unroll
        for (int j = 0; j < 8; j++) unpack2(acc[i][j], lo[j], hi[j]);

        float4 e0, e1, o0, o1;
        e0.x = __fadd_rn(__fsub_rn(qn0, __fmul_rn(2.f, lo[0])), kn[0]);
        e0.y = __fadd_rn(__fsub_rn(qn0, __fmul_rn(2.f, lo[1])), kn[1]);
        e0.z = __fadd_rn(__fsub_rn(qn0, __fmul_rn(2.f, lo[2])), kn[2]);
        e0.w = __fadd_rn(__fsub_rn(qn0, __fmul_rn(2.f, lo[3])), kn[3]);
        e1.x = __fadd_rn(__fsub_rn(qn0, __fmul_rn(2.f, lo[4])), kn[4]);
        e1.y = __fadd_rn(__fsub_rn(qn0, __fmul_rn(2.f, lo[5])), kn[5]);
        e1.z = __fadd_rn(__fsub_rn(qn0, __fmul_rn(2.f, lo[6])), kn[6]);
        e1.w = __fadd_rn(__fsub_rn(qn0, __fmul_rn(2.f, lo[7])), kn[7]);
        o0.x = __fadd_rn(__fsub_rn(qn1, __fmul_rn(2.f, hi[0])), kn[0]);
        o0.y = __fadd_rn(__fsub_rn(qn1, __fmul_rn(2.f, hi[1])), kn[1]);
        o0.z = __fadd_rn(__fsub_rn(qn1, __fmul_rn(2.f, hi[2])), kn[2]);
        o0.w = __fadd_rn(__fsub_rn(qn1, __fmul_rn(2.f, hi[3])), kn[3]);
        o1.x = __fadd_rn(__fsub_rn(qn1, __fmul_rn(2.f, hi[4])), kn[4]);
        o1.y = __fadd_rn(__fsub_rn(qn1, __fmul_rn(2.f, hi[5])), kn[5]);
        o1.z = __fadd_rn(__fsub_rn(qn1, __fmul_rn(2.f, hi[6])), kn[6]);
        o1.w = __fadd_rn(__fsub_rn(qn1, __fmul_rn(2.f, hi[7])), kn[7]);

        float* r0 = g_D + (size_t)gm * NKP + gn;
        float* r1 = g_D + (size_t)(gm + 1) * NKP + gn;
        reinterpret_cast<float4*>(r0)[0] = e0;
        reinterpret_cast<float4*>(r0 + 4)[0] = e1;
        reinterpret_cast<float4*>(r1)[0] = o0;
        reinterpret_cast<float4*>(r1 + 4)[0] = o1;
    }
}

// ---------------------------------------------------------------------------
// K3: per-query EXACT top-50 of the fp32 d values ((d, idx) order, same as
// lax.top_k), then fp64 weight epilogue (insensitive at ~1e-7).
// ---------------------------------------------------------------------------
#define CAP 2048

__device__ __forceinline__ void bitonic_sort(unsigned long long* keys, int tid)
{
    for (int k = 2; k <= CAP; k <<= 1) {
        for (int j = k >> 1; j > 0; j >>= 1) {
            #pragma unroll
            for (int t = 0; t < CAP / 256; t++) {
                int i = tid + t * 256;
                int ixj = i ^ j;
                if (ixj > i) {
                    bool up = ((i & k) == 0);
                    unsigned long long a = keys[i], b = keys[ixj];
                    if ((a > b) == up) { keys[i] = b; keys[ixj] = a; }
                }
            }
            __syncthreads();
        }
    }
}

__global__ __launch_bounds__(256) void select_kernel(
    const float* __restrict__ Q, const float* __restrict__ Kk,
    const float* __restrict__ V, float* __restrict__ out)
{
    __shared__ unsigned long long keys[CAP];
    __shared__ int   cnt;
    __shared__ float thr;
    __shared__ double d64s[KSEL];
    __shared__ __align__(16) float qs[DIM];

    const int q   = blockIdx.x;
    const int tid = threadIdx.x;

    if (tid == 0) { cnt = 0; thr = CUDART_INF_F; }
    if (tid < DIM) qs[tid] = Q[(size_t)q * DIM + tid];
    __syncthreads();

    const float4* Drow = reinterpret_cast<const float4*>(g_D + (size_t)q * NKP);
    const int n4 = NKP / 4;   // 25024

    for (int base = 0; base < n4; base += 256) {
        int i4 = base + tid;
        if (i4 < n4) {
            float4 v = Drow[i4];
            float t = thr;
            float dv[4] = {v.x, v.y, v.z, v.w};
            #pragma unroll
            for (int c = 0; c < 4; c++) {
                if (dv[c] <= t) {
                    int p = atomicAdd(&cnt, 1);
                    keys[p] = ((unsigned long long)__float_as_uint(dv[c]) << 32)
                              | (unsigned)(i4 * 4 + c);
                }
            }
        }
        __syncthreads();
        if (cnt > CAP - 1024) {            // flush: max 1024 inserts per round
            int c0 = cnt;
            for (int i = c0 + tid; i < CAP; i += 256) keys[i] = ~0ull;
            __syncthreads();
            bitonic_sort(keys, tid);
            if (tid == 0) {
                thr = __uint_as_float((unsigned)(keys[KSEL - 1] >> 32));
                cnt = KSEL;
            }
            for (int i = KSEL + tid; i < CAP; i += 256) keys[i] = ~0ull;
        }
        __syncthreads();
    }

    // final exact sort: keys[0..49] = top-50 of the fp32 d's by (d, idx)
    {
        int c0 = cnt;
        for (int i = c0 + tid; i < CAP; i += 256) keys[i] = ~0ull;
        __syncthreads();
        bitonic_sort(keys, tid);
    }

    // fp64 rescore of the 50 winners (weights insensitive to this precision).
    const int lane = tid & 31;
    const int w    = tid >> 5;
    for (int j = w; j < KSEL; j += 8) {
        unsigned idx = (unsigned)(keys[j] & 0xFFFFFFFFu);
        float4 kv = reinterpret_cast<const float4*>(Kk + (size_t)idx * DIM)[lane];
        float4 qv = reinterpret_cast<const float4*>(qs)[lane];
        double dx = (double)qv.x - (double)kv.x;
        double dy = (double)qv.y - (double)kv.y;
        double dz = (double)qv.z - (double)kv.z;
        double dw = (double)qv.w - (double)kv.w;
        double s = dx * dx + dy * dy + dz * dz + dw * dw;
        #pragma unroll
        for (int o = 16; o; o >>= 1) s += __shfl_xor_sync(0xFFFFFFFFu, s, o);
        if (lane == 0) d64s[j] = s;
    }
    __syncthreads();

    if (tid == 0) {
        double usum = 0.0;
        #pragma unroll 1
        for (int j = 0; j < KSEL; j++) usum += 1.0 / (d64s[j] + (double)DELTA);
        double o = 0.0;
        #pragma unroll 1
        for (int j = 0; j < KSEL; j++) {
            unsigned idx = (unsigned)(keys[j] & 0xFFFFFFFFu);
            o += (1.0 / (d64s[j] + (double)DELTA)) / usum * (double)V[idx];
        }
        out[q] = (float)o;
    }
}

// ---------------------------------------------------------------------------
extern "C" void kernel_launch(void* const* d_in, const int* in_sizes, int n_in,
                              void* d_out, int out_size)
{
    const float* Q  = (const float*)d_in[0];   // [2048, 128]
    const float* Kk = (const float*)d_in[1];   // [100000, 128]
    const float* V  = (const float*)d_in[2];   // [100000]
    float* out      = (float*)d_out;           // [2048, 1]

    // K1: norms, one thread per row, strict serial-scalar reduce.
    int rows = NQ + NKP;                       // 102144
    norms_kernel<<<(rows + 255) / 256, 256>>>(Q, Kk);

    // K2: distance matrix (FFMA2 GEMM).
    dim3 g2(NKP / TN, NQ / TM);                // (782, 16)
    dist_kernel<<<g2, 256>>>(Q, Kk);

    // K3: selection + aggregation.
    select_kernel<<<NQ, 256>>>(Q, Kk, V, out);
}

// round 12
// speedup vs baseline: 1.5615x; 1.1152x over previous
#include <cuda_runtime.h>
#include <cuda_bf16.h>
#include <math_constants.h>
#include <mma.h>

using namespace nvcuda;

// Problem constants
#define NQ   2048
#define NK   100000
#define NKP  100096          // padded to multiple of 128 (n-tile)
#define DIM  128
#define KSEL 50
#define DELTA 1e-3f
#define EPS  0.05f           // candidate margin >> bf16x3 split error (~1e-4)

// Scratch (device globals: allocation-free rule)
__device__ float g_D[(size_t)NQ * NKP];   // approx dot3 matrix (raw dot, fp32)
__device__ float g_qn[NQ];
__device__ float g_kn[NKP];
__device__ __nv_bfloat16 g_Qh[(size_t)NQ * DIM];
__device__ __nv_bfloat16 g_Ql[(size_t)NQ * DIM];
__device__ __nv_bfloat16 g_Kh[(size_t)NKP * DIM];
__device__ __nv_bfloat16 g_Kl[(size_t)NKP * DIM];

// ---------------------------------------------------------------------------
// K1: row norms, XLA:CPU strict reduce semantics: serial scalar chain in index
// order, multiply then add, NO fma. One thread per row. (Bit-exact, load-bearing.)
// ---------------------------------------------------------------------------
__global__ __launch_bounds__(256) void norms_kernel(
    const float* __restrict__ Q, const float* __restrict__ Kk)
{
    int i = blockIdx.x * blockDim.x + threadIdx.x;
    if (i >= NQ + NKP) return;

    const float* row;
    float* dst;
    if (i < NQ) {
        row = Q + (size_t)i * DIM;
        dst = &g_qn[i];
    } else {
        int n = i - NQ;
        if (n >= NK) { g_kn[n] = CUDART_INF_F; return; }
        row = Kk + (size_t)n * DIM;
        dst = &g_kn[n];
    }

    float acc = 0.f;
    const float4* r4 = reinterpret_cast<const float4*>(row);
    #pragma unroll 8
    for (int j = 0; j < DIM / 4; j++) {
        float4 v = __ldg(r4 + j);
        acc = __fadd_rn(acc, __fmul_rn(v.x, v.x));
        acc = __fadd_rn(acc, __fmul_rn(v.y, v.y));
        acc = __fadd_rn(acc, __fmul_rn(v.z, v.z));
        acc = __fadd_rn(acc, __fmul_rn(v.w, v.w));
    }
    *dst = acc;
}

// ---------------------------------------------------------------------------
// K1b: bf16 hi/lo split of Q and K (padded K rows -> 0).
// ---------------------------------------------------------------------------
__global__ __launch_bounds__(256) void prep_kernel(
    const float* __restrict__ Q, const float* __restrict__ Kk)
{
    size_t i = (size_t)blockIdx.x * blockDim.x + threadIdx.x;
    const size_t nq_elems = (size_t)NQ * DIM;
    const size_t total = nq_elems + (size_t)NKP * DIM;
    if (i >= total) return;

    if (i < nq_elems) {
        float x = Q[i];
        __nv_bfloat16 hi = __float2bfloat16(x);
        float lo = x - __bfloat162float(hi);
        g_Qh[i] = hi;
        g_Ql[i] = __float2bfloat16(lo);
    } else {
        size_t j = i - nq_elems;
        size_t n = j >> 7;
        float x = (n < NK) ? Kk[j] : 0.f;
        __nv_bfloat16 hi = __float2bfloat16(x);
        float lo = x - __bfloat162float(hi);
        g_Kh[j] = hi;
        g_Kl[j] = __float2bfloat16(lo);
    }
}

// ---------------------------------------------------------------------------
// K2: bf16x3 tensor-core GEMM. dot3 = Qh.Kh + Qh.Kl + Ql.Kh (fp32 accum).
// 128x128 CTA tile, 8 warps (2m x 4n), 4 k-chunks of 32. Raw dot stored in g_D;
// K3 applies qn/kn on the fly (approx path only).
// ---------------------------------------------------------------------------
#define GLD 40   // smem leading dim (bf16 elems), multiple of 8

__global__ __launch_bounds__(256) void gemm_kernel()
{
    __shared__ __nv_bfloat16 Ah[128 * GLD];
    __shared__ __nv_bfloat16 Al[128 * GLD];
    __shared__ __nv_bfloat16 Bh[128 * GLD];
    __shared__ __nv_bfloat16 Bl[128 * GLD];

    const int tid  = threadIdx.x;
    const int warp = tid >> 5;
    const int bm = blockIdx.y * 128;
    const int bn = blockIdx.x * 128;

    const int wm = (warp & 1) * 64;   // warp m-offset (64 rows)
    const int wn = (warp >> 1) * 32;  // warp n-offset (32 cols)

    wmma::fragment<wmma::accumulator, 16, 16, 16, float> acc[4][2];
    #pragma unroll
    for (int i = 0; i < 4; i++)
        #pragma unroll
        for (int j = 0; j < 2; j++)
            wmma::fill_fragment(acc[i][j], 0.f);

    #pragma unroll 1
    for (int kc = 0; kc < DIM; kc += 32) {
        // Load 128x32 bf16 tiles of Qh/Ql/Kh/Kl (4-elem = 8B chunks).
        #pragma unroll
        for (int it = 0; it < 4; it++) {
            int s  = tid + it * 256;      // 0..1023
            int r  = s >> 3;              // row 0..127
            int kq = (s & 7) << 2;        // 0,4,...,28
            size_t qo = (size_t)(bm + r) * DIM + kc + kq;
            size_t ko = (size_t)(bn + r) * DIM + kc + kq;
            *reinterpret_cast<uint2*>(&Ah[r * GLD + kq]) =
                *reinterpret_cast<const uint2*>(&g_Qh[qo]);
            *reinterpret_cast<uint2*>(&Al[r * GLD + kq]) =
                *reinterpret_cast<const uint2*>(&g_Ql[qo]);
            *reinterpret_cast<uint2*>(&Bh[r * GLD + kq]) =
                *reinterpret_cast<const uint2*>(&g_Kh[ko]);
            *reinterpret_cast<uint2*>(&Bl[r * GLD + kq]) =
                *reinterpret_cast<const uint2*>(&g_Kl[ko]);
        }
        __syncthreads();

        #pragma unroll
        for (int kk = 0; kk < 32; kk += 16) {
            wmma::fragment<wmma::matrix_a, 16, 16, 16, __nv_bfloat16, wmma::row_major> ah[4], al[4];
            wmma::fragment<wmma::matrix_b, 16, 16, 16, __nv_bfloat16, wmma::col_major> bh[2], bl[2];
            #pragma unroll
            for (int i = 0; i < 4; i++) {
                wmma::load_matrix_sync(ah[i], &Ah[(wm + i * 16) * GLD + kk], GLD);
                wmma::load_matrix_sync(al[i], &Al[(wm + i * 16) * GLD + kk], GLD);
            }
            #pragma unroll
            for (int j = 0; j < 2; j++) {
                wmma::load_matrix_sync(bh[j], &Bh[(wn + j * 16) * GLD + kk], GLD);
                wmma::load_matrix_sync(bl[j], &Bl[(wn + j * 16) * GLD + kk], GLD);
            }
            #pragma unroll
            for (int i = 0; i < 4; i++)
                #pragma unroll
                for (int j = 0; j < 2; j++) {
                    wmma::mma_sync(acc[i][j], ah[i], bh[j], acc[i][j]);
                    wmma::mma_sync(acc[i][j], ah[i], bl[j], acc[i][j]);
                    wmma::mma_sync(acc[i][j], al[i], bh[j], acc[i][j]);
                }
        }
        __syncthreads();
    }

    #pragma unroll
    for (int i = 0; i < 4; i++)
        #pragma unroll
        for (int j = 0; j < 2; j++)
            wmma::store_matrix_sync(
                g_D + (size_t)(bm + wm + i * 16) * NKP + (bn + wn + j * 16),
                acc[i][j], NKP, wmma::mem_row_major);
}

// ---------------------------------------------------------------------------
// K3: per-query selection. Stream approx d = qn - 2*dot3 + kn, keep EPS-superset
// of top-50; exact bit-identical rescore (serial __fmaf_rn chain, reference
// association) of the <=256 survivors; exact top-50 by (d_exact, idx); fp64
// weight epilogue (unchanged).
// ---------------------------------------------------------------------------
#define CAP 2048
#define MMAX 256

__device__ __forceinline__ void bitonic_sort(unsigned long long* keys, int tid)
{
    for (int k = 2; k <= CAP; k <<= 1) {
        for (int j = k >> 1; j > 0; j >>= 1) {
            #pragma unroll
            for (int t = 0; t < CAP / 256; t++) {
                int i = tid + t * 256;
                int ixj = i ^ j;
                if (ixj > i) {
                    bool up = ((i & k) == 0);
                    unsigned long long a = keys[i], b = keys[ixj];
                    if ((a > b) == up) { keys[i] = b; keys[ixj] = a; }
                }
            }
            __syncthreads();
        }
    }
}

// 256-element bitonic (one element per thread)
__device__ __forceinline__ void bitonic_sort256(unsigned long long* keys, int tid)
{
    for (int k = 2; k <= 256; k <<= 1) {
        for (int j = k >> 1; j > 0; j >>= 1) {
            int ixj = tid ^ j;
            if (ixj > tid) {
                bool up = ((tid & k) == 0);
                unsigned long long a = keys[tid], b = keys[ixj];
                if ((a > b) == up) { keys[tid] = b; keys[ixj] = a; }
            }
            __syncthreads();
        }
    }
}

__global__ __launch_bounds__(256) void select_kernel(
    const float* __restrict__ Q, const float* __restrict__ Kk,
    const float* __restrict__ V, float* __restrict__ out)
{
    __shared__ unsigned long long keys[CAP];
    __shared__ int   cnt;
    __shared__ int   cut;
    __shared__ float thr;
    __shared__ double d64s[KSEL];
    __shared__ __align__(16) float qs[DIM];

    const int q   = blockIdx.x;
    const int tid = threadIdx.x;
    const float qn = g_qn[q];

    if (tid == 0) { cnt = 0; thr = CUDART_INF_F; }
    if (tid < DIM) qs[tid] = Q[(size_t)q * DIM + tid];
    __syncthreads();

    const float4* Drow = reinterpret_cast<const float4*>(g_D + (size_t)q * NKP);
    const float4* Kn4  = reinterpret_cast<const float4*>(g_kn);
    const int n4 = NKP / 4;   // 25024

    for (int base = 0; base < n4; base += 256) {
        int i4 = base + tid;
        if (i4 < n4) {
            float4 v  = Drow[i4];
            float4 kv = Kn4[i4];
            float t = thr;
            float dv[4];
            dv[0] = qn - 2.f * v.x + kv.x;
            dv[1] = qn - 2.f * v.y + kv.y;
            dv[2] = qn - 2.f * v.z + kv.z;
            dv[3] = qn - 2.f * v.w + kv.w;
            #pragma unroll
            for (int c = 0; c < 4; c++) {
                if (dv[c] <= t) {
                    int p = atomicAdd(&cnt, 1);
                    keys[p] = ((unsigned long long)__float_as_uint(dv[c]) << 32)
                              | (unsigned)(i4 * 4 + c);
                }
            }
        }
        __syncthreads();
        if (cnt > CAP - 1024) {            // flush: max 1024 inserts per round
            int c0 = cnt;
            for (int i = c0 + tid; i < CAP; i += 256) keys[i] = ~0ull;
            if (tid == 0) cut = CAP;
            __syncthreads();
            bitonic_sort(keys, tid);
            float d50 = __uint_as_float((unsigned)(keys[KSEL - 1] >> 32));
            unsigned cutbits = __float_as_uint(d50 + EPS);
            #pragma unroll
            for (int t = 0; t < CAP / 256; t++) {
                int i = tid + t * 256;
                if ((unsigned)(keys[i] >> 32) > cutbits) atomicMin(&cut, i);
            }
            __syncthreads();
            int c = min(cut, 1024);
            if (tid == 0) { thr = d50 + EPS; cnt = c; }
            for (int i = c + tid; i < CAP; i += 256) keys[i] = ~0ull;
        }
        __syncthreads();
    }

    // final sort + EPS cut
    {
        int c0 = cnt;
        for (int i = c0 + tid; i < CAP; i += 256) keys[i] = ~0ull;
        if (tid == 0) cut = CAP;
        __syncthreads();
        bitonic_sort(keys, tid);
        float d50 = __uint_as_float((unsigned)(keys[KSEL - 1] >> 32));
        unsigned cutbits = __float_as_uint(d50 + EPS);
        #pragma unroll
        for (int t = 0; t < CAP / 256; t++) {
            int i = tid + t * 256;
            if ((unsigned)(keys[i] >> 32) > cutbits) atomicMin(&cut, i);
        }
        __syncthreads();
    }
    const int M = min(cut, MMAX);

    // Exact bit-identical rescore of survivors: serial __fmaf_rn chain over k
    // ascending, single accumulator; d = fadd(fsub(qn, 2*dot), kn). This is the
    // exact arithmetic that defined the passing selection in Rounds 10-11.
    {
        unsigned long long nk = ~0ull;
        if (tid < M) {
            unsigned idx = (unsigned)(keys[tid] & 0xFFFFFFFFu);
            const float4* kr = reinterpret_cast<const float4*>(Kk + (size_t)idx * DIM);
            const float4* qr = reinterpret_cast<const float4*>(qs);
            float acc = 0.f;
            #pragma unroll 8
            for (int j = 0; j < DIM / 4; j++) {
                float4 kv = __ldg(kr + j);
                float4 qv = qr[j];
                acc = __fmaf_rn(qv.x, kv.x, acc);
                acc = __fmaf_rn(qv.y, kv.y, acc);
                acc = __fmaf_rn(qv.z, kv.z, acc);
                acc = __fmaf_rn(qv.w, kv.w, acc);
            }
            float d = __fadd_rn(__fsub_rn(qn, __fmul_rn(2.f, acc)), g_kn[idx]);
            nk = ((unsigned long long)__float_as_uint(d) << 32) | idx;
        }
        __syncthreads();
        keys[tid] = nk;            // threads >= M write +INF sentinels
        __syncthreads();
        bitonic_sort256(keys, tid);
    }

    // fp64 rescore of the 50 winners (weights insensitive to this precision).
    const int lane = tid & 31;
    const int w    = tid >> 5;
    for (int j = w; j < KSEL; j += 8) {
        unsigned idx = (unsigned)(keys[j] & 0xFFFFFFFFu);
        float4 kv = reinterpret_cast<const float4*>(Kk + (size_t)idx * DIM)[lane];
        float4 qv = reinterpret_cast<const float4*>(qs)[lane];
        double dx = (double)qv.x - (double)kv.x;
        double dy = (double)qv.y - (double)kv.y;
        double dz = (double)qv.z - (double)kv.z;
        double dw = (double)qv.w - (double)kv.w;
        double s = dx * dx + dy * dy + dz * dz + dw * dw;
        #pragma unroll
        for (int o = 16; o; o >>= 1) s += __shfl_xor_sync(0xFFFFFFFFu, s, o);
        if (lane == 0) d64s[j] = s;
    }
    __syncthreads();

    if (tid == 0) {
        double usum = 0.0;
        #pragma unroll 1
        for (int j = 0; j < KSEL; j++) usum += 1.0 / (d64s[j] + (double)DELTA);
        double o = 0.0;
        #pragma unroll 1
        for (int j = 0; j < KSEL; j++) {
            unsigned idx = (unsigned)(keys[j] & 0xFFFFFFFFu);
            o += (1.0 / (d64s[j] + (double)DELTA)) / usum * (double)V[idx];
        }
        out[q] = (float)o;
    }
}

// ---------------------------------------------------------------------------
extern "C" void kernel_launch(void* const* d_in, const int* in_sizes, int n_in,
                              void* d_out, int out_size)
{
    const float* Q  = (const float*)d_in[0];   // [2048, 128]
    const float* Kk = (const float*)d_in[1];   // [100000, 128]
    const float* V  = (const float*)d_in[2];   // [100000]
    float* out      = (float*)d_out;           // [2048, 1]

    // K1: norms (bit-exact, strict serial-scalar reduce).
    int rows = NQ + NKP;
    norms_kernel<<<(rows + 255) / 256, 256>>>(Q, Kk);

    // K1b: bf16 hi/lo split.
    size_t elems = (size_t)(NQ + NKP) * DIM;
    prep_kernel<<<(int)((elems + 255) / 256), 256>>>(Q, Kk);

    // K2: bf16x3 tensor-core GEMM (raw dot3 into g_D).
    dim3 g2(NKP / 128, NQ / 128);              // (782, 16)
    gemm_kernel<<<g2, 256>>>();

    // K3: selection (EPS superset -> exact rescore) + aggregation.
    select_kernel<<<NQ, 256>>>(Q, Kk, V, out);
}

// round 15
// speedup vs baseline: 1.8154x; 1.1626x over previous
#include <cuda_runtime.h>
#include <cuda_bf16.h>
#include <math_constants.h>
#include <mma.h>

using namespace nvcuda;

// Problem constants
#define NQ   2048
#define NK   100000
#define NKP  100096          // padded to multiple of 128 (n-tile)
#define DIM  128
#define KSEL 50
#define DELTA 1e-3f
#define EPS  0.5f            // candidate margin >> dot2 approx error (max ~0.15)

// Scratch (device globals: allocation-free rule)
__device__ float g_D[(size_t)NQ * NKP];   // approx raw dot matrix (fp32)
__device__ float g_qn[NQ];
__device__ float g_kn[NKP];
__device__ float g_thr[NQ];
__device__ __nv_bfloat16 g_Qh[(size_t)NQ * DIM];
__device__ __nv_bfloat16 g_Kh[(size_t)NKP * DIM];
__device__ __nv_bfloat16 g_Kl[(size_t)NKP * DIM];

// ---------------------------------------------------------------------------
// K1: row norms, XLA:CPU strict reduce semantics: serial scalar chain in index
// order, multiply then add, NO fma. One thread per row. (Bit-exact, load-bearing.)
// ---------------------------------------------------------------------------
__global__ __launch_bounds__(256) void norms_kernel(
    const float* __restrict__ Q, const float* __restrict__ Kk)
{
    int i = blockIdx.x * blockDim.x + threadIdx.x;
    if (i >= NQ + NKP) return;

    const float* row;
    float* dst;
    if (i < NQ) {
        row = Q + (size_t)i * DIM;
        dst = &g_qn[i];
    } else {
        int n = i - NQ;
        if (n >= NK) { g_kn[n] = CUDART_INF_F; return; }
        row = Kk + (size_t)n * DIM;
        dst = &g_kn[n];
    }

    float acc = 0.f;
    const float4* r4 = reinterpret_cast<const float4*>(row);
    #pragma unroll 8
    for (int j = 0; j < DIM / 4; j++) {
        float4 v = __ldg(r4 + j);
        acc = __fadd_rn(acc, __fmul_rn(v.x, v.x));
        acc = __fadd_rn(acc, __fmul_rn(v.y, v.y));
        acc = __fadd_rn(acc, __fmul_rn(v.z, v.z));
        acc = __fadd_rn(acc, __fmul_rn(v.w, v.w));
    }
    *dst = acc;
}

// ---------------------------------------------------------------------------
// K1b: bf16 split. Q -> hi only; K -> hi + lo (dot2 = Qh.Kh + Qh.Kl).
// ---------------------------------------------------------------------------
__global__ __launch_bounds__(256) void prep_kernel(
    const float* __restrict__ Q, const float* __restrict__ Kk)
{
    size_t i = (size_t)blockIdx.x * blockDim.x + threadIdx.x;
    const size_t nq_elems = (size_t)NQ * DIM;
    const size_t total = nq_elems + (size_t)NKP * DIM;
    if (i >= total) return;

    if (i < nq_elems) {
        g_Qh[i] = __float2bfloat16(Q[i]);
    } else {
        size_t j = i - nq_elems;
        size_t n = j >> 7;
        float x = (n < NK) ? Kk[j] : 0.f;
        __nv_bfloat16 hi = __float2bfloat16(x);
        float lo = x - __bfloat162float(hi);
        g_Kh[j] = hi;
        g_Kl[j] = __float2bfloat16(lo);
    }
}

// ---------------------------------------------------------------------------
// K2: bf16x2 tensor-core GEMM. dot2 = Qh.Kh + Qh.Kl (fp32 accum).
// 128x128 CTA tile, 8 warps (2m x 4n). Raw dot stored in g_D.
// ---------------------------------------------------------------------------
#define GLD 40   // smem leading dim (bf16 elems), multiple of 8

__global__ __launch_bounds__(256) void gemm_kernel()
{
    __shared__ __nv_bfloat16 Ah[128 * GLD];
    __shared__ __nv_bfloat16 Bh[128 * GLD];
    __shared__ __nv_bfloat16 Bl[128 * GLD];

    const int tid  = threadIdx.x;
    const int warp = tid >> 5;
    const int bm = blockIdx.y * 128;
    const int bn = blockIdx.x * 128;

    const int wm = (warp & 1) * 64;   // warp m-offset (64 rows)
    const int wn = (warp >> 1) * 32;  // warp n-offset (32 cols)

    wmma::fragment<wmma::accumulator, 16, 16, 16, float> acc[4][2];
    #pragma unroll
    for (int i = 0; i < 4; i++)
        #pragma unroll
        for (int j = 0; j < 2; j++)
            wmma::fill_fragment(acc[i][j], 0.f);

    #pragma unroll 1
    for (int kc = 0; kc < DIM; kc += 32) {
        #pragma unroll
        for (int it = 0; it < 4; it++) {
            int s  = tid + it * 256;      // 0..1023
            int r  = s >> 3;              // row 0..127
            int kq = (s & 7) << 2;        // 0,4,...,28
            size_t qo = (size_t)(bm + r) * DIM + kc + kq;
            size_t ko = (size_t)(bn + r) * DIM + kc + kq;
            *reinterpret_cast<uint2*>(&Ah[r * GLD + kq]) =
                *reinterpret_cast<const uint2*>(&g_Qh[qo]);
            *reinterpret_cast<uint2*>(&Bh[r * GLD + kq]) =
                *reinterpret_cast<const uint2*>(&g_Kh[ko]);
            *reinterpret_cast<uint2*>(&Bl[r * GLD + kq]) =
                *reinterpret_cast<const uint2*>(&g_Kl[ko]);
        }
        __syncthreads();

        #pragma unroll
        for (int kk = 0; kk < 32; kk += 16) {
            wmma::fragment<wmma::matrix_a, 16, 16, 16, __nv_bfloat16, wmma::row_major> ah[4];
            wmma::fragment<wmma::matrix_b, 16, 16, 16, __nv_bfloat16, wmma::col_major> bh[2], bl[2];
            #pragma unroll
            for (int i = 0; i < 4; i++)
                wmma::load_matrix_sync(ah[i], &Ah[(wm + i * 16) * GLD + kk], GLD);
            #pragma unroll
            for (int j = 0; j < 2; j++) {
                wmma::load_matrix_sync(bh[j], &Bh[(wn + j * 16) * GLD + kk], GLD);
                wmma::load_matrix_sync(bl[j], &Bl[(wn + j * 16) * GLD + kk], GLD);
            }
            #pragma unroll
            for (int i = 0; i < 4; i++)
                #pragma unroll
                for (int j = 0; j < 2; j++) {
                    wmma::mma_sync(acc[i][j], ah[i], bh[j], acc[i][j]);
                    wmma::mma_sync(acc[i][j], ah[i], bl[j], acc[i][j]);
                }
        }
        __syncthreads();
    }

    #pragma unroll
    for (int i = 0; i < 4; i++)
        #pragma unroll
        for (int j = 0; j < 2; j++)
            wmma::store_matrix_sync(
                g_D + (size_t)(bm + wm + i * 16) * NKP + (bn + wn + j * 16),
                acc[i][j], NKP, wmma::mem_row_major);
}

// ---------------------------------------------------------------------------
// K2b: per-query fixed threshold from the first 4096 approx distances.
// Each of 256 threads takes the min of its 16 strided elements; the 64th
// smallest of those minima is a guaranteed upper bound on the sample's 64th
// order statistic -> F(thr) ~ 1.6-1.8% -> ~1780 expected keeps (buffer 4096).
// ---------------------------------------------------------------------------
#define THRSAMP 4096

__global__ __launch_bounds__(256) void thr_kernel()
{
    __shared__ unsigned mins[256];
    const int q   = blockIdx.x;
    const int tid = threadIdx.x;
    const float qn = g_qn[q];

    const float* Drow = g_D + (size_t)q * NKP;
    float m = CUDART_INF_F;
    #pragma unroll
    for (int t = 0; t < THRSAMP / 256; t++) {
        int i = tid + t * 256;
        float d = qn - 2.f * Drow[i] + g_kn[i];
        m = fminf(m, d);
    }
    mins[tid] = __float_as_uint(m);
    __syncthreads();

    // bitonic sort 256 (ascending; all values positive floats)
    for (int k = 2; k <= 256; k <<= 1) {
        for (int j = k >> 1; j > 0; j >>= 1) {
            int ixj = tid ^ j;
            if (ixj > tid) {
                bool up = ((tid & k) == 0);
                unsigned a = mins[tid], b = mins[ixj];
                if ((a > b) == up) { mins[tid] = b; mins[ixj] = a; }
            }
            __syncthreads();
        }
    }
    if (tid == 0) g_thr[q] = __uint_as_float(mins[63]);
}

// ---------------------------------------------------------------------------
// K3: per-query selection with FIXED threshold -> barrier-free streaming scan
// into a 4096-slot smem buffer; one bitonic sort; EPS cut; exact bit-identical
// rescore (serial __fmaf_rn chain, reference association); fp64 weights.
// ---------------------------------------------------------------------------
#define BUF 4096
#define MMAX 256

__device__ __forceinline__ void bitonic_sort_buf(unsigned long long* keys, int tid)
{
    for (int k = 2; k <= BUF; k <<= 1) {
        for (int j = k >> 1; j > 0; j >>= 1) {
            #pragma unroll
            for (int t = 0; t < BUF / 256; t++) {
                int i = tid + t * 256;
                int ixj = i ^ j;
                if (ixj > i) {
                    bool up = ((i & k) == 0);
                    unsigned long long a = keys[i], b = keys[ixj];
                    if ((a > b) == up) { keys[i] = b; keys[ixj] = a; }
                }
            }
            __syncthreads();
        }
    }
}

__device__ __forceinline__ void bitonic_sort256(unsigned long long* keys, int tid)
{
    for (int k = 2; k <= 256; k <<= 1) {
        for (int j = k >> 1; j > 0; j >>= 1) {
            int ixj = tid ^ j;
            if (ixj > tid) {
                bool up = ((tid & k) == 0);
                unsigned long long a = keys[tid], b = keys[ixj];
                if ((a > b) == up) { keys[tid] = b; keys[ixj] = a; }
            }
            __syncthreads();
        }
    }
}

__global__ __launch_bounds__(256) void select_kernel(
    const float* __restrict__ Q, const float* __restrict__ Kk,
    const float* __restrict__ V, float* __restrict__ out)
{
    __shared__ unsigned long long keys[BUF];
    __shared__ int   cnt;
    __shared__ int   cut;
    __shared__ double d64s[KSEL];
    __shared__ __align__(16) float qs[DIM];

    const int q   = blockIdx.x;
    const int tid = threadIdx.x;
    const float qn  = g_qn[q];
    const float thr = g_thr[q];

    if (tid == 0) { cnt = 0; cut = BUF; }
    if (tid < DIM) qs[tid] = Q[(size_t)q * DIM + tid];
    __syncthreads();

    // Barrier-free streaming filter (fixed thr; atomic inserts are rare).
    const float4* Drow = reinterpret_cast<const float4*>(g_D + (size_t)q * NKP);
    const float4* Kn4  = reinterpret_cast<const float4*>(g_kn);
    const int n4 = NKP / 4;   // 25024

    for (int i4 = tid; i4 < n4; i4 += 256) {
        float4 v  = Drow[i4];
        float4 kv = Kn4[i4];
        float dv[4];
        dv[0] = qn - 2.f * v.x + kv.x;
        dv[1] = qn - 2.f * v.y + kv.y;
        dv[2] = qn - 2.f * v.z + kv.z;
        dv[3] = qn - 2.f * v.w + kv.w;
        #pragma unroll
        for (int c = 0; c < 4; c++) {
            if (dv[c] <= thr) {
                int p = atomicAdd(&cnt, 1);
                if (p < BUF)
                    keys[p] = ((unsigned long long)__float_as_uint(dv[c]) << 32)
                              | (unsigned)(i4 * 4 + c);
            }
        }
    }
    __syncthreads();

    // Pad and sort once.
    {
        int c0 = min(cnt, BUF);
        for (int i = c0 + tid; i < BUF; i += 256) keys[i] = ~0ull;
        __syncthreads();
        bitonic_sort_buf(keys, tid);

        // EPS cut around the approx 50th.
        float d50 = __uint_as_float((unsigned)(keys[KSEL - 1] >> 32));
        unsigned cutbits = __float_as_uint(d50 + EPS);
        #pragma unroll
        for (int t = 0; t < BUF / 256; t++) {
            int i = tid + t * 256;
            if ((unsigned)(keys[i] >> 32) > cutbits) atomicMin(&cut, i);
        }
        __syncthreads();
    }
    const int M = min(cut, MMAX);

    // Exact bit-identical rescore: serial __fmaf_rn chain over k ascending,
    // single accumulator; d = fadd(fsub(qn, 2*dot), kn). (Defines selection.)
    {
        unsigned long long nk = ~0ull;
        if (tid < M) {
            unsigned idx = (unsigned)(keys[tid] & 0xFFFFFFFFu);
            const float4* kr = reinterpret_cast<const float4*>(Kk + (size_t)idx * DIM);
            const float4* qr = reinterpret_cast<const float4*>(qs);
            float acc = 0.f;
            #pragma unroll 8
            for (int j = 0; j < DIM / 4; j++) {
                float4 kv = __ldg(kr + j);
                float4 qv = qr[j];
                acc = __fmaf_rn(qv.x, kv.x, acc);
                acc = __fmaf_rn(qv.y, kv.y, acc);
                acc = __fmaf_rn(qv.z, kv.z, acc);
                acc = __fmaf_rn(qv.w, kv.w, acc);
            }
            float d = __fadd_rn(__fsub_rn(qn, __fmul_rn(2.f, acc)), g_kn[idx]);
            nk = ((unsigned long long)__float_as_uint(d) << 32) | idx;
        }
        __syncthreads();
        keys[tid] = nk;            // threads >= M write +INF sentinels
        __syncthreads();
        bitonic_sort256(keys, tid);
    }

    // fp64 rescore of the 50 winners (weights insensitive to this precision).
    const int lane = tid & 31;
    const int w    = tid >> 5;
    for (int j = w; j < KSEL; j += 8) {
        unsigned idx = (unsigned)(keys[j] & 0xFFFFFFFFu);
        float4 kv = reinterpret_cast<const float4*>(Kk + (size_t)idx * DIM)[lane];
        float4 qv = reinterpret_cast<const float4*>(qs)[lane];
        double dx = (double)qv.x - (double)kv.x;
        double dy = (double)qv.y - (double)kv.y;
        double dz = (double)qv.z - (double)kv.z;
        double dw = (double)qv.w - (double)kv.w;
        double s = dx * dx + dy * dy + dz * dz + dw * dw;
        #pragma unroll
        for (int o = 16; o; o >>= 1) s += __shfl_xor_sync(0xFFFFFFFFu, s, o);
        if (lane == 0) d64s[j] = s;
    }
    __syncthreads();

    if (tid == 0) {
        double usum = 0.0;
        #pragma unroll 1
        for (int j = 0; j < KSEL; j++) usum += 1.0 / (d64s[j] + (double)DELTA);
        double o = 0.0;
        #pragma unroll 1
        for (int j = 0; j < KSEL; j++) {
            unsigned idx = (unsigned)(keys[j] & 0xFFFFFFFFu);
            o += (1.0 / (d64s[j] + (double)DELTA)) / usum * (double)V[idx];
        }
        out[q] = (float)o;
    }
}

// ---------------------------------------------------------------------------
extern "C" void kernel_launch(void* const* d_in, const int* in_sizes, int n_in,
                              void* d_out, int out_size)
{
    const float* Q  = (const float*)d_in[0];   // [2048, 128]
    const float* Kk = (const float*)d_in[1];   // [100000, 128]
    const float* V  = (const float*)d_in[2];   // [100000]
    float* out      = (float*)d_out;           // [2048, 1]

    // K1: norms (bit-exact, strict serial-scalar reduce).
    int rows = NQ + NKP;
    norms_kernel<<<(rows + 255) / 256, 256>>>(Q, Kk);

    // K1b: bf16 split (Qh, Kh, Kl).
    size_t elems = (size_t)(NQ + NKP) * DIM;
    prep_kernel<<<(int)((elems + 255) / 256), 256>>>(Q, Kk);

    // K2: bf16x2 tensor-core GEMM (raw dot2 into g_D).
    dim3 g2(NKP / 128, NQ / 128);              // (782, 16)
    gemm_kernel<<<g2, 256>>>();

    // K2b: per-query fixed thresholds.
    thr_kernel<<<NQ, 256>>>();

    // K3: selection (fixed-thr syncless scan -> exact rescore) + aggregation.
    select_kernel<<<NQ, 256>>>(Q, Kk, V, out);
}